// round 1
// baseline (speedup 1.0000x reference)
#include <cuda_runtime.h>

// CausalWindowedAttention: B=2,H=16,S=2048,D=64, window=256, temp=8
// Output = concat(out[B,H,S,D], attn[B,H,S,S]) as float32.

#define SQ    2048
#define DH    64
#define MT    64              // queries per CTA tile
#define WIN   256
#define KR    (MT + WIN)      // 320 key rows covering the tile's union window
#define KPAD  68              // padded row (floats) for conflict-free LDS
#define SPAD  (KR + 1)        // 321: score row pad
#define NTH   256

// smem layout (floats)
#define SM_Q  0
#define SM_K  (MT * DH)                 // 4096
#define SM_S  (SM_K + KR * KPAD)        // 25856
#define SM_TOT (SM_S + MT * SPAD)       // 46400 floats = 185600 B

__global__ void __launch_bounds__(NTH, 1)
cwa_kernel(const float* __restrict__ q,
           const float* __restrict__ k,
           const float* __restrict__ v,
           float* __restrict__ out,    // [BH, SQ, DH]
           float* __restrict__ attn)   // [BH, SQ, SQ]
{
    extern __shared__ float sm[];
    float* sQ = sm + SM_Q;
    float* sK = sm + SM_K;   // reused for V later
    float* sS = sm + SM_S;

    const int tile = blockIdx.x;
    const int bh   = blockIdx.y;
    const int i0   = tile * MT;
    const int tid  = threadIdx.x;
    const int lane = tid & 31;
    const int w    = tid >> 5;

    const size_t base = (size_t)bh * SQ * DH;
    const int jn0 = i0 - (WIN - 1);   // key j for smem row n: j = jn0 + n

    // ---- load Q tile (64 x 64) ----
    {
        const float4* qg = (const float4*)(q + base + (size_t)i0 * DH);
        float4* qs = (float4*)sQ;
        #pragma unroll
        for (int idx = tid; idx < MT * (DH / 4); idx += NTH)
            qs[idx] = qg[idx];
    }
    // ---- load K window (320 rows, zero-fill OOB) ----
    for (int idx = tid; idx < KR * (DH / 4); idx += NTH) {
        int n = idx >> 4;
        int c = idx & 15;
        int j = jn0 + n;
        float4 val = make_float4(0.f, 0.f, 0.f, 0.f);
        if (j >= 0 && j < SQ)
            val = *(const float4*)(k + base + (size_t)j * DH + c * 4);
        *(float4*)&sK[n * KPAD + c * 4] = val;
    }
    __syncthreads();

    // ---- scores: warp w handles rows m0..m0+7, lane covers n = lane + 32*ni ----
    {
        const int m0 = w * 8;
        float acc[8][10];
        #pragma unroll
        for (int mi = 0; mi < 8; mi++)
            #pragma unroll
            for (int ni = 0; ni < 10; ni++)
                acc[mi][ni] = 0.f;

        #pragma unroll 1
        for (int dc = 0; dc < DH / 4; dc++) {
            float4 q4[8];
            #pragma unroll
            for (int mi = 0; mi < 8; mi++)
                q4[mi] = *(const float4*)&sQ[(m0 + mi) * DH + dc * 4];
            #pragma unroll
            for (int ni = 0; ni < 10; ni++) {
                const int n = lane + ni * 32;
                float4 k4 = *(const float4*)&sK[n * KPAD + dc * 4];
                #pragma unroll
                for (int mi = 0; mi < 8; mi++) {
                    acc[mi][ni] += q4[mi].x * k4.x;
                    acc[mi][ni] += q4[mi].y * k4.y;
                    acc[mi][ni] += q4[mi].z * k4.z;
                    acc[mi][ni] += q4[mi].w * k4.w;
                }
            }
        }
        #pragma unroll
        for (int mi = 0; mi < 8; mi++)
            #pragma unroll
            for (int ni = 0; ni < 10; ni++)
                sS[(m0 + mi) * SPAD + lane + ni * 32] = acc[mi][ni] * 0.125f; // 1/temperature
    }
    __syncthreads();

    // ---- softmax per row (warp w owns rows w*8..w*8+7) ----
    {
        const int m0 = w * 8;
        #pragma unroll 1
        for (int r = 0; r < 8; r++) {
            const int m = m0 + r;
            const int nlo = max(m, (WIN - 1) - i0);  // j>=0 clamp
            const int nhi = m + (WIN - 1);           // <= 318

            float mx = -1e30f;
            for (int n = nlo + lane; n <= nhi; n += 32)
                mx = fmaxf(mx, sS[m * SPAD + n]);
            #pragma unroll
            for (int o = 16; o; o >>= 1)
                mx = fmaxf(mx, __shfl_xor_sync(0xffffffffu, mx, o));

            float sum = 0.f;
            for (int n = nlo + lane; n <= nhi; n += 32) {
                float e = __expf(sS[m * SPAD + n] - mx);
                sS[m * SPAD + n] = e;
                sum += e;
            }
            #pragma unroll
            for (int o = 16; o; o >>= 1)
                sum += __shfl_xor_sync(0xffffffffu, sum, o);

            const float inv = 1.f / sum;
            for (int n = lane; n < KR; n += 32) {
                float val = (n >= nlo && n <= nhi) ? sS[m * SPAD + n] * inv : 0.f;
                sS[m * SPAD + n] = val;   // normalized probs; zeros outside window
            }
        }
    }
    __syncthreads();

    // ---- load V into the K buffer (probs are final in sS) ----
    for (int idx = tid; idx < KR * (DH / 4); idx += NTH) {
        int n = idx >> 4;
        int c = idx & 15;
        int j = jn0 + n;
        float4 val = make_float4(0.f, 0.f, 0.f, 0.f);
        if (j >= 0 && j < SQ)
            val = *(const float4*)(v + base + (size_t)j * DH + c * 4);
        *(float4*)&sK[n * KPAD + c * 4] = val;
    }

    // ---- write dense attn rows (zeros outside window), coalesced float4 ----
    {
        const size_t attn_base = (size_t)bh * SQ * SQ;
        #pragma unroll 1
        for (int m = 0; m < MT; m++) {
            const int i = i0 + m;
            float4* dst = (float4*)(attn + attn_base + (size_t)i * SQ);
            for (int idx = tid; idx < SQ / 4; idx += NTH) {
                const int j = idx * 4;
                float4 val;
                float* vp = &val.x;
                #pragma unroll
                for (int c = 0; c < 4; c++) {
                    const int jj = j + c;
                    const unsigned di = (unsigned)(i - jj);
                    vp[c] = (di < (unsigned)WIN) ? sS[m * SPAD + (jj - jn0)] : 0.f;
                }
                dst[idx] = val;
            }
        }
    }
    __syncthreads();

    // ---- PV: thread owns 4 m-rows x 4 d-cols ----
    {
        const int dq = tid & 15;    // d-group: cols dq*4..dq*4+3
        const int mb = (tid >> 4) * 4;

        float4 a0 = make_float4(0, 0, 0, 0);
        float4 a1 = make_float4(0, 0, 0, 0);
        float4 a2 = make_float4(0, 0, 0, 0);
        float4 a3 = make_float4(0, 0, 0, 0);

        #pragma unroll 4
        for (int n = 0; n < KR; n++) {
            const float4 v4 = *(const float4*)&sK[n * KPAD + dq * 4];
            const float p0 = sS[(mb + 0) * SPAD + n];
            const float p1 = sS[(mb + 1) * SPAD + n];
            const float p2 = sS[(mb + 2) * SPAD + n];
            const float p3 = sS[(mb + 3) * SPAD + n];
            a0.x += p0 * v4.x; a0.y += p0 * v4.y; a0.z += p0 * v4.z; a0.w += p0 * v4.w;
            a1.x += p1 * v4.x; a1.y += p1 * v4.y; a1.z += p1 * v4.z; a1.w += p1 * v4.w;
            a2.x += p2 * v4.x; a2.y += p2 * v4.y; a2.z += p2 * v4.z; a2.w += p2 * v4.w;
            a3.x += p3 * v4.x; a3.y += p3 * v4.y; a3.z += p3 * v4.z; a3.w += p3 * v4.w;
        }

        float4* o0 = (float4*)(out + base + (size_t)(i0 + mb + 0) * DH + dq * 4);
        float4* o1 = (float4*)(out + base + (size_t)(i0 + mb + 1) * DH + dq * 4);
        float4* o2 = (float4*)(out + base + (size_t)(i0 + mb + 2) * DH + dq * 4);
        float4* o3 = (float4*)(out + base + (size_t)(i0 + mb + 3) * DH + dq * 4);
        *o0 = a0; *o1 = a1; *o2 = a2; *o3 = a3;
    }
}

extern "C" void kernel_launch(void* const* d_in, const int* in_sizes, int n_in,
                              void* d_out, int out_size)
{
    const float* q = (const float*)d_in[0];
    const float* k = (const float*)d_in[1];
    const float* v = (const float*)d_in[2];

    // BH = total q elements / (S*D)
    const int BH = in_sizes[0] / (SQ * DH);   // 32

    float* out  = (float*)d_out;
    float* attn = out + (size_t)BH * SQ * DH;

    cudaFuncSetAttribute(cwa_kernel,
                         cudaFuncAttributeMaxDynamicSharedMemorySize,
                         SM_TOT * (int)sizeof(float));

    dim3 grid(SQ / MT, BH);
    cwa_kernel<<<grid, NTH, SM_TOT * sizeof(float)>>>(q, k, v, out, attn);
    (void)n_in; (void)out_size;
}

// round 2
// speedup vs baseline: 1.2470x; 1.2470x over previous
#include <cuda_runtime.h>

// CausalWindowedAttention: B=2,H=16,S=2048,D=64, window=256, temp=8
// Output = concat(out[B,H,S,D], attn[B,H,S,S]) as float32.

#define SQ    2048
#define DH    64
#define MT    64              // queries per CTA tile
#define WIN   256
#define KR    320             // valid key rows for the tile window union
#define KRA   352             // allocated key rows (zero-padded tail)
#define KPAD  68              // padded K/V row (floats)
#define SPAD  353             // score row stride (floats)
#define NTH   512

// smem layout (floats)
#define SM_Q   0
#define SM_K   (MT * DH)                  // 4096
#define SM_S   (SM_K + KRA * KPAD)        // 4096 + 23936 = 28032
#define SM_TOT (SM_S + MT * SPAD)         // 28032 + 22592 = 50624 floats = 202496 B

__device__ __forceinline__ void ffma2(unsigned long long& d,
                                      unsigned long long a,
                                      unsigned long long b) {
    asm("fma.rn.f32x2 %0, %1, %2, %0;" : "+l"(d) : "l"(a), "l"(b));
}
__device__ __forceinline__ unsigned long long pk2(float x) {
    unsigned long long r;
    asm("mov.b64 %0, {%1, %1};" : "=l"(r) : "f"(x));
    return r;
}
__device__ __forceinline__ float unpk_sum(unsigned long long a) {
    float lo, hi;
    asm("mov.b64 {%0, %1}, %2;" : "=f"(lo), "=f"(hi) : "l"(a));
    return lo + hi;
}

__global__ void __launch_bounds__(NTH, 1)
cwa_kernel(const float* __restrict__ q,
           const float* __restrict__ k,
           const float* __restrict__ v,
           float* __restrict__ out,    // [BH, SQ, DH]
           float* __restrict__ attn)   // [BH, SQ, SQ]
{
    extern __shared__ float sm[];
    float* sQ = sm + SM_Q;
    float* sK = sm + SM_K;   // reused for V later
    float* sS = sm + SM_S;

    const int tile = blockIdx.x;
    const int bh   = blockIdx.y;
    const int i0   = tile * MT;
    const int tid  = threadIdx.x;
    const int lane = tid & 31;
    const int w    = tid >> 5;

    const size_t base = (size_t)bh * SQ * DH;
    const int jn0 = i0 - (WIN - 1);   // key j for smem row n: j = jn0 + n

    // ---- load Q tile (64 x 64) ----
    {
        const float4* qg = (const float4*)(q + base + (size_t)i0 * DH);
        float4* qs = (float4*)sQ;
        for (int idx = tid; idx < MT * (DH / 4); idx += NTH)
            qs[idx] = qg[idx];
    }
    // ---- load K window (352 rows, zero-fill OOB) ----
    for (int idx = tid; idx < KRA * (DH / 4); idx += NTH) {
        int n = idx >> 4;
        int c = idx & 15;
        int j = jn0 + n;
        float4 val = make_float4(0.f, 0.f, 0.f, 0.f);
        if (j >= 0 && j < SQ)
            val = *(const float4*)(k + base + (size_t)j * DH + c * 4);
        *(float4*)&sK[n * KPAD + c * 4] = val;
    }
    __syncthreads();

    // ---- scores: warp w -> rows m0..m0+3, keys n = m0 + lane + 32*ni, ni<9 ----
    {
        const int m0 = w * 4;
        int nb[9];
        #pragma unroll
        for (int ni = 0; ni < 9; ni++)
            nb[ni] = (m0 + lane + 32 * ni) * KPAD;

        unsigned long long acc[4][9];
        #pragma unroll
        for (int mi = 0; mi < 4; mi++)
            #pragma unroll
            for (int ni = 0; ni < 9; ni++)
                acc[mi][ni] = 0ULL;

        #pragma unroll 1
        for (int dc = 0; dc < DH / 4; dc++) {
            ulonglong2 q2[4];
            #pragma unroll
            for (int mi = 0; mi < 4; mi++)
                q2[mi] = *(const ulonglong2*)&sQ[(m0 + mi) * DH + dc * 4];
            #pragma unroll
            for (int ni = 0; ni < 9; ni++) {
                ulonglong2 k2 = *(const ulonglong2*)&sK[nb[ni] + dc * 4];
                #pragma unroll
                for (int mi = 0; mi < 4; mi++) {
                    ffma2(acc[mi][ni], q2[mi].x, k2.x);
                    ffma2(acc[mi][ni], q2[mi].y, k2.y);
                }
            }
        }
        #pragma unroll
        for (int mi = 0; mi < 4; mi++)
            #pragma unroll
            for (int ni = 0; ni < 9; ni++)
                sS[(m0 + mi) * SPAD + m0 + lane + 32 * ni] =
                    unpk_sum(acc[mi][ni]) * 0.125f;   // 1/temperature
    }
    __syncthreads();

    // ---- softmax per row (warp w owns rows w*4..w*4+3), zero outside window ----
    {
        const int m0 = w * 4;
        #pragma unroll 1
        for (int r = 0; r < 4; r++) {
            const int m = m0 + r;
            const int nlo = max(m, (WIN - 1) - i0);  // j>=0 clamp
            const int nhi = m + (WIN - 1);

            float mx = -1e30f;
            for (int n = nlo + lane; n <= nhi; n += 32)
                mx = fmaxf(mx, sS[m * SPAD + n]);
            #pragma unroll
            for (int o = 16; o; o >>= 1)
                mx = fmaxf(mx, __shfl_xor_sync(0xffffffffu, mx, o));

            float sum = 0.f;
            for (int n = nlo + lane; n <= nhi; n += 32) {
                float e = __expf(sS[m * SPAD + n] - mx);
                sS[m * SPAD + n] = e;
                sum += e;
            }
            #pragma unroll
            for (int o = 16; o; o >>= 1)
                sum += __shfl_xor_sync(0xffffffffu, sum, o);

            const float inv = 1.f / sum;
            for (int n = lane; n < KRA; n += 32) {
                float val = (n >= nlo && n <= nhi) ? sS[m * SPAD + n] * inv : 0.f;
                sS[m * SPAD + n] = val;
            }
        }
    }
    __syncthreads();

    if (tid < 256) {
        // ===== warps 0-7: load V, then PV, write out =====
        for (int idx = tid; idx < KR * (DH / 4); idx += 256) {
            int n = idx >> 4;
            int c = idx & 15;
            int j = jn0 + n;
            float4 val = make_float4(0.f, 0.f, 0.f, 0.f);
            if (j >= 0 && j < SQ)
                val = *(const float4*)(v + base + (size_t)j * DH + c * 4);
            *(float4*)&sK[n * KPAD + c * 4] = val;
        }
        asm volatile("bar.sync 1, 256;" ::: "memory");

        const int dq = tid & 15;          // d-group: cols dq*4..dq*4+3
        const int mg = tid >> 4;          // row group: rows mg*4..mg*4+3
        const float* pbase = sS + (mg * 4) * SPAD;

        unsigned long long axy[4], azw[4];
        #pragma unroll
        for (int r = 0; r < 4; r++) { axy[r] = 0ULL; azw[r] = 0ULL; }

        #pragma unroll 4
        for (int n = 0; n < KR; n++) {
            ulonglong2 v2 = *(const ulonglong2*)&sK[n * KPAD + dq * 4];
            #pragma unroll
            for (int r = 0; r < 4; r++) {
                unsigned long long p2 = pk2(pbase[r * SPAD + n]);
                ffma2(axy[r], p2, v2.x);
                ffma2(azw[r], p2, v2.y);
            }
        }
        #pragma unroll
        for (int r = 0; r < 4; r++) {
            ulonglong2 o;
            o.x = axy[r];
            o.y = azw[r];
            *(ulonglong2*)(out + base + (size_t)(i0 + mg * 4 + r) * DH + dq * 4) = o;
        }
    } else {
        // ===== warps 8-15: stream dense attn rows (zeros + band) =====
        const int tw = tid - 256;
        const int lw = tw & 31;
        const int ww = tw >> 5;           // 0..7, rows ww*8..ww*8+7
        const size_t attn_base = (size_t)bh * SQ * SQ;
        const float4 z4 = make_float4(0.f, 0.f, 0.f, 0.f);

        #pragma unroll 1
        for (int rr = 0; rr < 8; rr++) {
            const int m = ww * 8 + rr;
            const int i = i0 + m;
            const int jlo = max(0, i - (WIN - 1));
            float4* dst = (float4*)(attn + attn_base + (size_t)i * SQ);
            const float* srow = sS + m * SPAD - jn0;   // srow[j] = prob(i, j)

            for (int idx = lw; idx < SQ / 4; idx += 32) {
                const int j4 = idx * 4;
                float4 val;
                if (j4 + 3 < jlo || j4 > i) {
                    val = z4;
                } else {
                    float* vp = &val.x;
                    #pragma unroll
                    for (int c = 0; c < 4; c++) {
                        const int j = j4 + c;
                        vp[c] = (j >= jlo && j <= i) ? srow[j] : 0.f;
                    }
                }
                dst[idx] = val;
            }
        }
    }
}

extern "C" void kernel_launch(void* const* d_in, const int* in_sizes, int n_in,
                              void* d_out, int out_size)
{
    const float* q = (const float*)d_in[0];
    const float* k = (const float*)d_in[1];
    const float* v = (const float*)d_in[2];

    const int BH = in_sizes[0] / (SQ * DH);   // 32

    float* out  = (float*)d_out;
    float* attn = out + (size_t)BH * SQ * DH;

    cudaFuncSetAttribute(cwa_kernel,
                         cudaFuncAttributeMaxDynamicSharedMemorySize,
                         SM_TOT * (int)sizeof(float));

    dim3 grid(SQ / MT, BH);
    cwa_kernel<<<grid, NTH, SM_TOT * sizeof(float)>>>(q, k, v, out, attn);
    (void)n_in; (void)out_size;
}